// round 15
// baseline (speedup 1.0000x reference)
#include <cuda_runtime.h>
#include <cuda_fp16.h>
#include <cstdint>

// Live computation (GNN branch is dead code in the reference):
//   h1 = relu(sf @ Wfc1^T + bfc1)     [N,12] -> [N,64]   (HMMA fp16, K padded to 16)
//   h2 = relu(h1 @ Wfc2^T + bfc2)     [N,64] -> [N,64]   (HMMA fp16, A register-chained)
//   out = h2 @ Wp^T + bp              [N,64] -> [N,1]    (HMMA projection, Wp replicated)
//
// Epilogues in packed half2 (hadd2/hmax2); final projection as 4 MMAs with Wp
// replicated across all 8 N-columns (result lands in every lane, no shuffle
// reduce). Register-chain identities: D1 n-pair == A2 k-tile, relu(D2) n-pair
// == A3 k-tile.

#define NN     100000
#define SF     12
#define FC     64
#define TPB    256
#define NPB    128
#define GRID   296            // exactly 2 CTAs/SM on 148 SMs -> single wave
#define NTMAX  3              // ceil(782 / 296)
#define BSTR   144            // W2 smem row stride (bytes): 9x16B, conflict-free
#define WSTR   48             // W1 smem row stride (bytes): 3x16B, conflict-free

// ---- dynamic smem layout (byte offsets) ----
#define OFF_B2H  0            // 64 x 144 (W2 as f16)
#define OFF_W1H  9216         // 64 x 48  (W1 as f16, K padded to 16)
#define OFF_B1H  12288        // half2[32]  (b1 pairs)
#define OFF_B2HH 12416        // half2[32]  (b2 pairs)
#define OFF_WP   12544        // float[64]
#define OFF_BP   12800        // float
#define SMEM_DYN 12816

__device__ __forceinline__ uint32_t smem_u32(const void* p) {
    uint32_t a;
    asm("{ .reg .u64 t; cvta.to.shared.u64 t, %1; cvt.u32.u64 %0, t; }"
        : "=r"(a) : "l"(p));
    return a;
}
// pack: f0 -> low f16, f1 -> high f16
__device__ __forceinline__ uint32_t f16x2_of(float f0, float f1) {
    uint32_t r;
    asm("cvt.rn.f16x2.f32 %0, %1, %2;" : "=r"(r) : "f"(f1), "f"(f0));
    return r;
}
__device__ __forceinline__ __half2 u2h(uint32_t u) { return *reinterpret_cast<__half2*>(&u); }
__device__ __forceinline__ uint32_t h2u(__half2 h) { return *reinterpret_cast<uint32_t*>(&h); }

__device__ __forceinline__ void ldsm_x4(uint32_t* r, uint32_t addr) {
    asm volatile("ldmatrix.sync.aligned.m8n8.x4.shared.b16 {%0,%1,%2,%3}, [%4];"
                 : "=r"(r[0]), "=r"(r[1]), "=r"(r[2]), "=r"(r[3]) : "r"(addr));
}
__device__ __forceinline__ void mma_f16(float* d, const uint32_t* a, const uint32_t* b) {
    asm volatile(
        "mma.sync.aligned.m16n8k16.row.col.f32.f16.f16.f32 "
        "{%0,%1,%2,%3}, {%4,%5,%6,%7}, {%8,%9}, {%0,%1,%2,%3};"
        : "+f"(d[0]), "+f"(d[1]), "+f"(d[2]), "+f"(d[3])
        : "r"(a[0]), "r"(a[1]), "r"(a[2]), "r"(a[3]), "r"(b[0]), "r"(b[1]));
}

__global__ __launch_bounds__(TPB, 2)
void fused_mlp_hmma8(const float* __restrict__ sf,
                     const float* __restrict__ W1, const float* __restrict__ b1,
                     const float* __restrict__ W2, const float* __restrict__ b2,
                     const float* __restrict__ Wp, const float* __restrict__ bp,
                     float* __restrict__ out)
{
    extern __shared__ __align__(16) char base[];
    const uint32_t sb = smem_u32(base);

    const int tid  = threadIdx.x;
    const int lane = tid & 31;
    const int w    = tid >> 5;          // 0..7
    const int q    = lane & 3;
    const int r4   = lane >> 2;

    // ---- stage W2 -> f16 rows (row j = 64 f16 k-contig, stride 144) ----
    {
        const int row = tid >> 2, quarter = tid & 3;   // 16 floats per thread
        const float* src = W2 + row * FC + quarter * 16;
        #pragma unroll
        for (int g = 0; g < 2; g++) {
            float4 v0 = *(const float4*)(src + g * 8);
            float4 v1 = *(const float4*)(src + g * 8 + 4);
            const int off = row * BSTR + quarter * 32 + g * 16;
            *(uint4*)(base + OFF_B2H + off) =
                make_uint4(f16x2_of(v0.x, v0.y), f16x2_of(v0.z, v0.w),
                           f16x2_of(v1.x, v1.y), f16x2_of(v1.z, v1.w));
        }
    }
    // ---- stage W1 -> f16 rows (12 f16 + 4 zero pad per row, stride 48) ----
    if (tid < FC) {
        const float* src = W1 + tid * SF;
        float4 v0 = *(const float4*)(src);
        float4 v1 = *(const float4*)(src + 4);
        float4 v2 = *(const float4*)(src + 8);
        const int off = tid * WSTR;
        *(uint4*)(base + OFF_W1H + off) =
            make_uint4(f16x2_of(v0.x, v0.y), f16x2_of(v0.z, v0.w),
                       f16x2_of(v1.x, v1.y), f16x2_of(v1.z, v1.w));
        *(uint4*)(base + OFF_W1H + off + 16) =
            make_uint4(f16x2_of(v2.x, v2.y), f16x2_of(v2.z, v2.w), 0u, 0u);
    }
    // ---- stage biases as half2 pairs; Wp fp32 ----
    if (tid < 32) {
        float2 vb1 = *(const float2*)(b1 + 2 * tid);
        float2 vb2 = *(const float2*)(b2 + 2 * tid);
        ((uint32_t*)(base + OFF_B1H))[tid]  = f16x2_of(vb1.x, vb1.y);
        ((uint32_t*)(base + OFF_B2HH))[tid] = f16x2_of(vb2.x, vb2.y);
    }
    if (tid >= 32 && tid < 96) ((float*)(base + OFF_WP))[tid - 32] = Wp[tid - 32];
    if (tid == 0) *((float*)(base + OFF_BP)) = bp[0];

    const int local = lane & 7, mat = lane >> 3;
    const int kc = mat & 1, ntoff = mat >> 1;

    // ---- prefetch tile 0's sf values ----
    float2 v00 = make_float2(0.f, 0.f), v01 = v00, v10 = v00, v11 = v00;
    {
        const int mb = blockIdx.x * NPB + w * 16;
        const int row0 = mb + r4, row1 = row0 + 8;
        if (row0 < NN) {
            v00 = *(const float2*)(sf + (size_t)row0 * SF + 2 * q);
            if (q < 2) v01 = *(const float2*)(sf + (size_t)row0 * SF + 2 * q + 8);
        }
        if (row1 < NN) {
            v10 = *(const float2*)(sf + (size_t)row1 * SF + 2 * q);
            if (q < 2) v11 = *(const float2*)(sf + (size_t)row1 * SF + 2 * q + 8);
        }
    }
    __syncthreads();   // smem staged; read-only from here (loop is sync-free)

    const float bps = *((const float*)(base + OFF_BP));

    // ---- B3: Wp replicated across all 8 N columns (fragment regs col-free) ----
    uint32_t B3[4][2];
    {
        const float* wp = (const float*)(base + OFF_WP);
        #pragma unroll
        for (int kt = 0; kt < 4; kt++) {
            B3[kt][0] = f16x2_of(wp[16 * kt + 2 * q],     wp[16 * kt + 2 * q + 1]);
            B3[kt][1] = f16x2_of(wp[16 * kt + 2 * q + 8], wp[16 * kt + 2 * q + 9]);
        }
    }
    const __half2 z2 = __float2half2_rn(0.0f);

    for (int t = 0; t < NTMAX; t++) {
        const int tile = blockIdx.x + t * GRID;
        if (tile * NPB >= NN) break;
        const int mbase = tile * NPB + w * 16;

        // ---- layer-1 A fragments: plain fp16 ----
        uint32_t A1[4];
        A1[0] = f16x2_of(v00.x, v00.y);
        A1[1] = f16x2_of(v10.x, v10.y);
        A1[2] = f16x2_of(v01.x, v01.y);
        A1[3] = f16x2_of(v11.x, v11.y);

        // ---- prefetch next tile's sf (overlaps with all MMA phases) ----
        v00 = make_float2(0.f, 0.f); v01 = v00; v10 = v00; v11 = v00;
        {
            const int ntile = tile + GRID;
            if (t + 1 < NTMAX && ntile * NPB < NN) {
                const int mb = ntile * NPB + w * 16;
                const int row0 = mb + r4, row1 = row0 + 8;
                if (row0 < NN) {
                    v00 = *(const float2*)(sf + (size_t)row0 * SF + 2 * q);
                    if (q < 2) v01 = *(const float2*)(sf + (size_t)row0 * SF + 2 * q + 8);
                }
                if (row1 < NN) {
                    v10 = *(const float2*)(sf + (size_t)row1 * SF + 2 * q);
                    if (q < 2) v11 = *(const float2*)(sf + (size_t)row1 * SF + 2 * q + 8);
                }
            }
        }

        // ---- layer-1 MMA: 8 independent chains ----
        float D1[8][4];
        {
            uint32_t B1h[8][2];
            #pragma unroll
            for (int p = 0; p < 4; p++) {
                const uint32_t roff = ((2 * p + ntoff) * 8 + local) * WSTR + kc * 16;
                uint32_t r[4];
                ldsm_x4(r, sb + OFF_W1H + roff);
                B1h[2 * p][0] = r[0]; B1h[2 * p][1] = r[1];
                B1h[2 * p + 1][0] = r[2]; B1h[2 * p + 1][1] = r[3];
            }
            #pragma unroll
            for (int n = 0; n < 8; n++) {
                #pragma unroll
                for (int c = 0; c < 4; c++) D1[n][c] = 0.0f;
            }
            #pragma unroll
            for (int n = 0; n < 8; n++) mma_f16(D1[n], A1, B1h[n]);
        }

        // ---- epilogue-1 (half2): relu(D1 + b1) -> A2 fragments ----
        // k-tile kt of layer-2 A == D1 n-tiles {2kt, 2kt+1}.
        uint32_t A2[4][4];
        #pragma unroll
        for (int n = 0; n < 8; n++) {
            const __half2 bb = u2h(((const uint32_t*)(base + OFF_B1H))[n * 4 + q]);
            __half2 x0 = u2h(f16x2_of(D1[n][0], D1[n][1]));
            __half2 x1 = u2h(f16x2_of(D1[n][2], D1[n][3]));
            x0 = __hmax2(__hadd2(x0, bb), z2);
            x1 = __hmax2(__hadd2(x1, bb), z2);
            const int kt = n >> 1, o = (n & 1) * 2;
            A2[kt][o]     = h2u(x0);
            A2[kt][o + 1] = h2u(x1);
        }

        // ---- layer-2 MMA: term-major per kt, 8 independent chains ----
        float D2[8][4];
        #pragma unroll
        for (int n = 0; n < 8; n++)
            #pragma unroll
            for (int c = 0; c < 4; c++) D2[n][c] = 0.0f;

        #pragma unroll
        for (int kt = 0; kt < 4; kt++) {
            uint32_t bh[4][4];
            #pragma unroll
            for (int p = 0; p < 4; p++) {
                const uint32_t roff = ((2 * p + ntoff) * 8 + local) * BSTR + kt * 32 + kc * 16;
                ldsm_x4(bh[p], sb + OFF_B2H + roff);
            }
            #pragma unroll
            for (int p = 0; p < 4; p++) {
                mma_f16(D2[2 * p],     A2[kt], &bh[p][0]);
                mma_f16(D2[2 * p + 1], A2[kt], &bh[p][2]);
            }
        }

        // ---- epilogue-2 (half2): relu(D2 + b2) -> A3 fragments ----
        uint32_t A3[4][4];
        #pragma unroll
        for (int n = 0; n < 8; n++) {
            const __half2 bb = u2h(((const uint32_t*)(base + OFF_B2HH))[n * 4 + q]);
            __half2 x0 = u2h(f16x2_of(D2[n][0], D2[n][1]));
            __half2 x1 = u2h(f16x2_of(D2[n][2], D2[n][3]));
            x0 = __hmax2(__hadd2(x0, bb), z2);
            x1 = __hmax2(__hadd2(x1, bb), z2);
            const int kt = n >> 1, o = (n & 1) * 2;
            A3[kt][o]     = h2u(x0);
            A3[kt][o + 1] = h2u(x1);
        }

        // ---- projection: D3 = A3 * B3 (Wp replicated; all lanes get result) ----
        float D3[4] = {0.0f, 0.0f, 0.0f, 0.0f};
        #pragma unroll
        for (int kt = 0; kt < 4; kt++) mma_f16(D3, A3[kt], B3[kt]);

        if (q == 0) {
            const int n0 = mbase + r4;
            if (n0 < NN)     out[n0]     = D3[0] + bps;
            if (n0 + 8 < NN) out[n0 + 8] = D3[2] + bps;
        }
    }
}

extern "C" void kernel_launch(void* const* d_in, const int* in_sizes, int n_in,
                              void* d_out, int out_size)
{
    const float* sf = (const float*)d_in[2];
    const float* W1 = (const float*)d_in[9];
    const float* b1 = (const float*)d_in[10];
    const float* W2 = (const float*)d_in[11];
    const float* b2 = (const float*)d_in[12];
    const float* Wp = (const float*)d_in[13];
    const float* bp = (const float*)d_in[14];
    float* out = (float*)d_out;

    cudaFuncSetAttribute(fused_mlp_hmma8,
                         cudaFuncAttributeMaxDynamicSharedMemorySize, SMEM_DYN);
    fused_mlp_hmma8<<<GRID, TPB, SMEM_DYN>>>(sf, W1, b1, W2, b2, Wp, bp, out);
}

// round 16
// speedup vs baseline: 1.0656x; 1.0656x over previous
#include <cuda_runtime.h>
#include <cuda_fp16.h>
#include <cstdint>

// Live computation (GNN branch is dead code in the reference):
//   h1 = relu(sf @ Wfc1^T + bfc1)     [N,12] -> [N,64]   (HMMA fp16; b1 folded into K-pad col 12)
//   h2 = relu(h1 @ Wfc2^T + bfc2)     [N,64] -> [N,64]   (HMMA fp16, A register-chained)
//   out = h2 @ Wp^T + bp              [N,64] -> [N,1]    (HMMA projection, Wp replicated)
//
// Round 16: instruction-diet round.
//  - mma with C=0 operand (RZ) -> kills 68 accumulator-zeroing MOVs per tile
//  - b1 folded into W1 pad column 12 (A has constant f16 1.0 at k=12, lane q==2)
//  - B1h fragments hoisted out of the tile loop (tile-invariant)
//  - projection split into 2 independent 2-MMA chains

#define NN     100000
#define SF     12
#define FC     64
#define TPB    256
#define NPB    128
#define GRID   296            // exactly 2 CTAs/SM on 148 SMs -> single wave
#define NTMAX  3              // ceil(782 / 296)
#define BSTR   144            // W2 smem row stride (bytes): 9x16B, conflict-free
#define WSTR   48             // W1 smem row stride (bytes): 3x16B, conflict-free

// ---- dynamic smem layout (byte offsets) ----
#define OFF_B2H  0            // 64 x 144 (W2 as f16)
#define OFF_W1H  9216         // 64 x 48  (W1 as f16, K padded to 16; col12 = b1)
#define OFF_B2HH 12288        // half2[32]  (b2 pairs)
#define OFF_WP   12416        // float[64]
#define OFF_BP   12672        // float
#define SMEM_DYN 12688

__device__ __forceinline__ uint32_t smem_u32(const void* p) {
    uint32_t a;
    asm("{ .reg .u64 t; cvta.to.shared.u64 t, %1; cvt.u32.u64 %0, t; }"
        : "=r"(a) : "l"(p));
    return a;
}
// pack: f0 -> low f16, f1 -> high f16
__device__ __forceinline__ uint32_t f16x2_of(float f0, float f1) {
    uint32_t r;
    asm("cvt.rn.f16x2.f32 %0, %1, %2;" : "=r"(r) : "f"(f1), "f"(f0));
    return r;
}
__device__ __forceinline__ __half2 u2h(uint32_t u) { return *reinterpret_cast<__half2*>(&u); }
__device__ __forceinline__ uint32_t h2u(__half2 h) { return *reinterpret_cast<uint32_t*>(&h); }

__device__ __forceinline__ void ldsm_x4(uint32_t* r, uint32_t addr) {
    asm volatile("ldmatrix.sync.aligned.m8n8.x4.shared.b16 {%0,%1,%2,%3}, [%4];"
                 : "=r"(r[0]), "=r"(r[1]), "=r"(r[2]), "=r"(r[3]) : "r"(addr));
}
// accumulate: D += A*B
__device__ __forceinline__ void mma_f16(float* d, const uint32_t* a, const uint32_t* b) {
    asm volatile(
        "mma.sync.aligned.m16n8k16.row.col.f32.f16.f16.f32 "
        "{%0,%1,%2,%3}, {%4,%5,%6,%7}, {%8,%9}, {%0,%1,%2,%3};"
        : "+f"(d[0]), "+f"(d[1]), "+f"(d[2]), "+f"(d[3])
        : "r"(a[0]), "r"(a[1]), "r"(a[2]), "r"(a[3]), "r"(b[0]), "r"(b[1]));
}
// initialize: D = A*B + 0   (C reads RZ -> no zeroing MOVs)
__device__ __forceinline__ void mma_f16_c0(float* d, const uint32_t* a, const uint32_t* b) {
    asm volatile(
        "mma.sync.aligned.m16n8k16.row.col.f32.f16.f16.f32 "
        "{%0,%1,%2,%3}, {%4,%5,%6,%7}, {%8,%9}, {%10,%10,%10,%10};"
        : "=f"(d[0]), "=f"(d[1]), "=f"(d[2]), "=f"(d[3])
        : "r"(a[0]), "r"(a[1]), "r"(a[2]), "r"(a[3]), "r"(b[0]), "r"(b[1]),
          "f"(0.0f));
}

__global__ __launch_bounds__(TPB, 2)
void fused_mlp_hmma9(const float* __restrict__ sf,
                     const float* __restrict__ W1, const float* __restrict__ b1,
                     const float* __restrict__ W2, const float* __restrict__ b2,
                     const float* __restrict__ Wp, const float* __restrict__ bp,
                     float* __restrict__ out)
{
    extern __shared__ __align__(16) char base[];
    const uint32_t sb = smem_u32(base);

    const int tid  = threadIdx.x;
    const int lane = tid & 31;
    const int w    = tid >> 5;          // 0..7
    const int q    = lane & 3;
    const int r4   = lane >> 2;

    // ---- stage W2 -> f16 rows (row j = 64 f16 k-contig, stride 144) ----
    {
        const int row = tid >> 2, quarter = tid & 3;   // 16 floats per thread
        const float* src = W2 + row * FC + quarter * 16;
        #pragma unroll
        for (int g = 0; g < 2; g++) {
            float4 v0 = *(const float4*)(src + g * 8);
            float4 v1 = *(const float4*)(src + g * 8 + 4);
            const int off = row * BSTR + quarter * 32 + g * 16;
            *(uint4*)(base + OFF_B2H + off) =
                make_uint4(f16x2_of(v0.x, v0.y), f16x2_of(v0.z, v0.w),
                           f16x2_of(v1.x, v1.y), f16x2_of(v1.z, v1.w));
        }
    }
    // ---- stage W1 -> f16 rows (12 f16 + b1 at col 12 + zero pad, stride 48) ----
    if (tid < FC) {
        const float* src = W1 + tid * SF;
        float4 v0 = *(const float4*)(src);
        float4 v1 = *(const float4*)(src + 4);
        float4 v2 = *(const float4*)(src + 8);
        const float bias1 = b1[tid];
        const int off = tid * WSTR;
        *(uint4*)(base + OFF_W1H + off) =
            make_uint4(f16x2_of(v0.x, v0.y), f16x2_of(v0.z, v0.w),
                       f16x2_of(v1.x, v1.y), f16x2_of(v1.z, v1.w));
        *(uint4*)(base + OFF_W1H + off + 16) =
            make_uint4(f16x2_of(v2.x, v2.y), f16x2_of(v2.z, v2.w),
                       f16x2_of(bias1, 0.0f), 0u);   // col12 = b1[j]
    }
    // ---- stage b2 as half2 pairs; Wp fp32 ----
    if (tid < 32) {
        float2 vb2 = *(const float2*)(b2 + 2 * tid);
        ((uint32_t*)(base + OFF_B2HH))[tid] = f16x2_of(vb2.x, vb2.y);
    }
    if (tid >= 32 && tid < 96) ((float*)(base + OFF_WP))[tid - 32] = Wp[tid - 32];
    if (tid == 0) *((float*)(base + OFF_BP)) = bp[0];

    const int local = lane & 7, mat = lane >> 3;
    const int kc = mat & 1, ntoff = mat >> 1;

    // ---- prefetch tile 0's sf values ----
    float2 v00 = make_float2(0.f, 0.f), v01 = v00, v10 = v00, v11 = v00;
    {
        const int mb = blockIdx.x * NPB + w * 16;
        const int row0 = mb + r4, row1 = row0 + 8;
        if (row0 < NN) {
            v00 = *(const float2*)(sf + (size_t)row0 * SF + 2 * q);
            if (q < 2) v01 = *(const float2*)(sf + (size_t)row0 * SF + 2 * q + 8);
        }
        if (row1 < NN) {
            v10 = *(const float2*)(sf + (size_t)row1 * SF + 2 * q);
            if (q < 2) v11 = *(const float2*)(sf + (size_t)row1 * SF + 2 * q + 8);
        }
    }
    __syncthreads();   // smem staged; read-only from here (loop is sync-free)

    const float bps = *((const float*)(base + OFF_BP));

    // ---- B3: Wp replicated across all 8 N columns (fragment regs col-free) ----
    uint32_t B3[4][2];
    {
        const float* wp = (const float*)(base + OFF_WP);
        #pragma unroll
        for (int kt = 0; kt < 4; kt++) {
            B3[kt][0] = f16x2_of(wp[16 * kt + 2 * q],     wp[16 * kt + 2 * q + 1]);
            B3[kt][1] = f16x2_of(wp[16 * kt + 2 * q + 8], wp[16 * kt + 2 * q + 9]);
        }
    }
    // ---- B1h fragments: tile-invariant, hoisted out of the loop ----
    uint32_t B1h[8][2];
    #pragma unroll
    for (int p = 0; p < 4; p++) {
        const uint32_t roff = ((2 * p + ntoff) * 8 + local) * WSTR + kc * 16;
        uint32_t r[4];
        ldsm_x4(r, sb + OFF_W1H + roff);
        B1h[2 * p][0] = r[0]; B1h[2 * p][1] = r[1];
        B1h[2 * p + 1][0] = r[2]; B1h[2 * p + 1][1] = r[3];
    }
    // A pad fragment value: k=12 carries the constant 1.0 that multiplies b1.
    // q==2 covers k pairs (12,13): low half = 1.0 (0x3C00). Other q: 0.
    const uint32_t padc = (q == 2) ? 0x00003C00u : 0u;
    const __half2 z2 = __float2half2_rn(0.0f);

    for (int t = 0; t < NTMAX; t++) {
        const int tile = blockIdx.x + t * GRID;
        if (tile * NPB >= NN) break;
        const int mbase = tile * NPB + w * 16;

        // ---- layer-1 A fragments: plain fp16 (+ bias-activation column) ----
        uint32_t A1[4];
        A1[0] = f16x2_of(v00.x, v00.y);
        A1[1] = f16x2_of(v10.x, v10.y);
        A1[2] = (q < 2) ? f16x2_of(v01.x, v01.y) : padc;
        A1[3] = (q < 2) ? f16x2_of(v11.x, v11.y) : padc;

        // ---- prefetch next tile's sf (overlaps with all MMA phases) ----
        v00 = make_float2(0.f, 0.f); v01 = v00; v10 = v00; v11 = v00;
        {
            const int ntile = tile + GRID;
            if (t + 1 < NTMAX && ntile * NPB < NN) {
                const int mb = ntile * NPB + w * 16;
                const int row0 = mb + r4, row1 = row0 + 8;
                if (row0 < NN) {
                    v00 = *(const float2*)(sf + (size_t)row0 * SF + 2 * q);
                    if (q < 2) v01 = *(const float2*)(sf + (size_t)row0 * SF + 2 * q + 8);
                }
                if (row1 < NN) {
                    v10 = *(const float2*)(sf + (size_t)row1 * SF + 2 * q);
                    if (q < 2) v11 = *(const float2*)(sf + (size_t)row1 * SF + 2 * q + 8);
                }
            }
        }

        // ---- layer-1 MMA: D1 = A1*W1 (+b1 via pad col), C=0 operand ----
        float D1[8][4];
        #pragma unroll
        for (int n = 0; n < 8; n++) mma_f16_c0(D1[n], A1, B1h[n]);

        // ---- epilogue-1 (half2): relu -> A2 fragments (bias already in D1) ----
        // k-tile kt of layer-2 A == D1 n-tiles {2kt, 2kt+1}.
        uint32_t A2[4][4];
        #pragma unroll
        for (int n = 0; n < 8; n++) {
            __half2 x0 = __hmax2(u2h(f16x2_of(D1[n][0], D1[n][1])), z2);
            __half2 x1 = __hmax2(u2h(f16x2_of(D1[n][2], D1[n][3])), z2);
            const int kt = n >> 1, o = (n & 1) * 2;
            A2[kt][o]     = h2u(x0);
            A2[kt][o + 1] = h2u(x1);
        }

        // ---- layer-2 MMA: term-major per kt; kt==0 uses C=0 form ----
        float D2[8][4];
        #pragma unroll
        for (int kt = 0; kt < 4; kt++) {
            uint32_t bh[4][4];
            #pragma unroll
            for (int p = 0; p < 4; p++) {
                const uint32_t roff = ((2 * p + ntoff) * 8 + local) * BSTR + kt * 32 + kc * 16;
                ldsm_x4(bh[p], sb + OFF_B2H + roff);
            }
            if (kt == 0) {
                #pragma unroll
                for (int p = 0; p < 4; p++) {
                    mma_f16_c0(D2[2 * p],     A2[0], &bh[p][0]);
                    mma_f16_c0(D2[2 * p + 1], A2[0], &bh[p][2]);
                }
            } else {
                #pragma unroll
                for (int p = 0; p < 4; p++) {
                    mma_f16(D2[2 * p],     A2[kt], &bh[p][0]);
                    mma_f16(D2[2 * p + 1], A2[kt], &bh[p][2]);
                }
            }
        }

        // ---- epilogue-2 (half2): relu(D2 + b2) -> A3 fragments ----
        uint32_t A3[4][4];
        #pragma unroll
        for (int n = 0; n < 8; n++) {
            const __half2 bb = u2h(((const uint32_t*)(base + OFF_B2HH))[n * 4 + q]);
            __half2 x0 = __hmax2(__hadd2(u2h(f16x2_of(D2[n][0], D2[n][1])), bb), z2);
            __half2 x1 = __hmax2(__hadd2(u2h(f16x2_of(D2[n][2], D2[n][3])), bb), z2);
            const int kt = n >> 1, o = (n & 1) * 2;
            A3[kt][o]     = h2u(x0);
            A3[kt][o + 1] = h2u(x1);
        }

        // ---- projection: two independent 2-MMA chains, then merge ----
        float D3a[4], D3b[4];
        mma_f16_c0(D3a, A3[0], B3[0]);
        mma_f16_c0(D3b, A3[2], B3[2]);
        mma_f16(D3a, A3[1], B3[1]);
        mma_f16(D3b, A3[3], B3[3]);

        if (q == 0) {
            const int n0 = mbase + r4;
            if (n0 < NN)     out[n0]     = (D3a[0] + D3b[0]) + bps;
            if (n0 + 8 < NN) out[n0 + 8] = (D3a[2] + D3b[2]) + bps;
        }
    }
}

extern "C" void kernel_launch(void* const* d_in, const int* in_sizes, int n_in,
                              void* d_out, int out_size)
{
    const float* sf = (const float*)d_in[2];
    const float* W1 = (const float*)d_in[9];
    const float* b1 = (const float*)d_in[10];
    const float* W2 = (const float*)d_in[11];
    const float* b2 = (const float*)d_in[12];
    const float* Wp = (const float*)d_in[13];
    const float* bp = (const float*)d_in[14];
    float* out = (float*)d_out;

    cudaFuncSetAttribute(fused_mlp_hmma9,
                         cudaFuncAttributeMaxDynamicSharedMemorySize, SMEM_DYN);
    fused_mlp_hmma9<<<GRID, TPB, SMEM_DYN>>>(sf, W1, b1, W2, b2, Wp, bp, out);
}